// round 12
// baseline (speedup 1.0000x reference)
#include <cuda_runtime.h>
#include <cuda_fp16.h>

#define Wd 1024
#define Hd 1024
#define Bd 4
#define Cd 4
#define HWd (Wd * Hd)
#define PI_F 3.14159265358979323846f

// Tiling: 32x32 output tile, 512 threads (32x16), 2 px/thread, |r| < 21 halo
#define Rh 21
#define TILE_X 32
#define TILE_Y 32
#define HALO_W (TILE_X + 2 * Rh)   // 74
#define HALO_H (TILE_Y + 2 * Rh)   // 74
#define HALO_S 75                  // padded row stride
#define NSMP 224
#define NTHREADS 512

#define EH_SCALE   1024.0f
#define EH_INV     (1.0f / 1024.0f)

__device__ __forceinline__ float tanh_fast(float x) {
    float y;
    asm("tanh.approx.f32 %0, %1;" : "=f"(y) : "f"(x));
    return y;
}

// ---------------------------------------------------------------------------
// Inner sample loop, 2 px/thread, split 8B+4B records.
// Dedup reuse is bit-exact (same offset => same records).
// CLAMP=false only for interior blocks (removing inactive clamps is exact).
// ---------------------------------------------------------------------------
template <bool CLAMP>
__device__ __forceinline__ void sample_loop(
    const float4* __restrict__ s_smp, int cnt,
    const uint2*  __restrict__ pimg,   // s_img + (-oy*HALO_S - ox)
    const unsigned* __restrict__ pse,  // s_se  + (-oy*HALO_S - ox)
    float r0, float r1, float he0, float he1,
    float pxg, float py0, float py1,
    float* acc)                        // 10 floats: a0..a3,aw for j=0,1
{
    int      poff0 = -1, poff1 = -1;
    uint2    ci0 = make_uint2(0u, 0u), ci1 = ci0;
    unsigned cs0 = 0u, cs1 = 0u;

    for (int k = 0; k < cnt; k++) {
        float4 s = s_smp[k];
        #pragma unroll
        for (int j = 0; j < 2; j++) {
            float rj  = j ? r1 : r0;
            float hej = j ? he1 : he0;
            float pyg = j ? py1 : py0;

            // rounding in GLOBAL coords — matches reference exactly
            float fx = fmaf(rj, s.x, pxg);
            float fy = fmaf(rj, s.y, pyg);
            int sx = __float2int_rn(fx);
            int sy = __float2int_rn(fy);
            if (CLAMP) {
                sx = min(max(sx, 0), Wd - 1);
                sy = min(max(sy, 0), Hd - 1);
            }
            int off = sy * HALO_S + sx;

            uint2 ui; unsigned us;
            if (j == 0) {
                if (off != poff0) { ci0 = pimg[off]; cs0 = pse[off]; poff0 = off; }
                ui = ci0; us = cs0;
            } else {
                if (off != poff1) { ci1 = pimg[off]; cs1 = pse[off]; poff1 = off; }
                ui = ci1; us = cs1;
            }

            // decode scalars (deterministic; same result on dedup hits)
            float A   = __half2float(__ushort_as_half((unsigned short)(us & 0xffffu)));
            float Ehf = (float)(us >> 16);            // Eh * 1024

            // t/2 = Eh_q + 0.5 - 0.5*eta*|r|*||s||
            float d  = fmaf(-hej, s.z, 0.5f);
            float t2 = fmaf(Ehf, EH_INV, d);
            float w  = A * fmaf(0.5f, tanh_fast(t2), 0.5f);   // A_q * sigmoid(t)

            float2 f01 = __half22float2(*reinterpret_cast<__half2*>(&ui.x));
            float2 f23 = __half22float2(*reinterpret_cast<__half2*>(&ui.y));

            float* ac = acc + j * 5;
            ac[0] = fmaf(w, f01.x, ac[0]);
            ac[1] = fmaf(w, f01.y, ac[1]);
            ac[2] = fmaf(w, f23.x, ac[2]);
            ac[3] = fmaf(w, f23.y, ac[3]);
            ac[4] += w;
        }
    }
}

// ---------------------------------------------------------------------------
// Fused kernel: per-CTA aperture table (serpentine), split-record halo fill
// from raw inputs, then render the 32x32 tile.
// SMEM layout (alignment-safe): [s_smp float4 NSMP][s_cnt][pad][s_img uint2][s_se u32]
// ---------------------------------------------------------------------------
__global__ __launch_bounds__(NTHREADS, 2)
void render_kernel(const float* __restrict__ img,
                   const float* __restrict__ alpha,
                   const float* __restrict__ coff,
                   const float* __restrict__ K,
                   const float* __restrict__ df,
                   const float* __restrict__ Eta,
                   const int*   __restrict__ spc,
                   float* __restrict__ out) {
    extern __shared__ unsigned char smem_raw[];
    float4*   s_smp = reinterpret_cast<float4*>(smem_raw);               // 16B aligned
    int*      s_cnt = reinterpret_cast<int*>(s_smp + NSMP);              // 4B
    uint2*    s_img = reinterpret_cast<uint2*>(smem_raw + NSMP * 16 + 16); // 8B aligned
    unsigned* s_se  = reinterpret_cast<unsigned*>(s_img + HALO_H * HALO_S); // 4B aligned

    int tid  = threadIdx.y * TILE_X + threadIdx.x;
    int lane = tid & 31;
    int b    = blockIdx.z;
    int base = b * HWd;
    int x0 = blockIdx.x * TILE_X;
    int y0 = blockIdx.y * TILE_Y;
    int ox = x0 - Rh;
    int oy = y0 - Rh;

    float Kb = __ldg(&K[b]);
    float db = __ldg(&df[b]);
    float eb = __ldg(&Eta[b]);
    float heb = 0.5f * eb;

    // --- warp 0: build compacted aperture table, serpentine j within rows ---
    if (tid < 32) {
        int n = 17;
        if (spc) { int v = spc[0]; if (v >= 2 && v <= 512) n = v; }
        float step = 2.0f / (float)(n - 1);
        int total = n * n;
        int c = 0;
        for (int bs = 0; bs < total; bs += 32) {
            int id = bs + lane;
            int i = id / n, j = id - i * n;
            int js = (i & 1) ? (n - 1 - j) : j;      // serpentine
            float xs = -1.0f + (float)i  * step;
            float ys = -1.0f + (float)js * step;
            float d2 = xs * xs + ys * ys;
            bool pred = (id < total) && (d2 <= 1.0f);
            unsigned m = __ballot_sync(0xffffffffu, pred);
            if (pred) {
                int off = c + __popc(m & ((1u << lane) - 1u));
                if (off < NSMP) s_smp[off] = make_float4(xs, ys, sqrtf(d2), 0.0f);
            }
            c += __popc(m);
        }
        if (lane == 0) *s_cnt = (c < NSMP) ? c : NSMP;
    }

    // --- halo fill: split records computed from raw inputs ---
    // img: 4x half (8B).  se: {half A | unorm16 Eh*1024} (4B),
    // A = alpha/(pi r^2+1), Eh = 0.5*eta*|r|.
    {
        const float* i0p = img + (size_t)b * Cd * HWd;
        for (int idx = tid; idx < HALO_H * HALO_W; idx += NTHREADS) {
            int hy = idx / HALO_W;
            int hx = idx - hy * HALO_W;
            int gx = min(max(ox + hx, 0), Wd - 1);
            int gy = min(max(oy + hy, 0), Hd - 1);
            int q  = (gy << 10) + gx;

            float c0 = __ldg(i0p + 0 * HWd + q);
            float c1 = __ldg(i0p + 1 * HWd + q);
            float c2 = __ldg(i0p + 2 * HWd + q);
            float c3 = __ldg(i0p + 3 * HWd + q);
            float al = __ldg(alpha + base + q);
            float cf = __ldg(coff  + base + q);

            float r  = Kb * (cf - db);
            float ra = fabsf(r);
            float A  = __fdividef(al, fmaf(PI_F * ra, ra, 1.0f));
            float Eh = heb * ra;

            __half2 h01 = __floats2half2_rn(c0, c1);
            __half2 h23 = __floats2half2_rn(c2, c3);
            uint2 rec;
            rec.x = *reinterpret_cast<unsigned*>(&h01);
            rec.y = *reinterpret_cast<unsigned*>(&h23);

            unsigned a_bits  = (unsigned)__half_as_ushort(__float2half_rn(A));
            unsigned eh_bits = (unsigned)__float2int_rn(Eh * EH_SCALE);  // <= 53760
            int so = hy * HALO_S + hx;
            s_img[so] = rec;
            s_se[so]  = a_bits | (eh_bits << 16);
        }
    }
    __syncthreads();
    int cnt = *s_cnt;

    int x   = x0 + threadIdx.x;
    int y0t = y0 + threadIdx.y;          // j=0 row
    int y1t = y0t + 16;                  // j=1 row

    float r0 = Kb * (__ldg(&coff[base + (y0t << 10) + x]) - db);
    float r1 = Kb * (__ldg(&coff[base + (y1t << 10) + x]) - db);
    float he0 = heb * fabsf(r0);
    float he1 = heb * fabsf(r1);

    // base pointers folding the halo offset (GLOBAL sy,sx indexing)
    const uint2*    pimg = s_img - (oy * HALO_S + ox);
    const unsigned* pse  = s_se  - (oy * HALO_S + ox);

    float acc[10];
    #pragma unroll
    for (int i = 0; i < 10; i++) acc[i] = 0.f;

    bool interior = (ox >= 0) && (ox + HALO_W <= Wd) && (oy >= 0) && (oy + HALO_H <= Hd);
    if (interior) {
        sample_loop<false>(s_smp, cnt, pimg, pse, r0, r1, he0, he1,
                           (float)x, (float)y0t, (float)y1t, acc);
    } else {
        sample_loop<true>(s_smp, cnt, pimg, pse, r0, r1, he0, he1,
                          (float)x, (float)y0t, (float)y1t, acc);
    }

    size_t ob = (size_t)b * Cd * HWd;
    #pragma unroll
    for (int j = 0; j < 2; j++) {
        int y = j ? y1t : y0t;
        int p = (y << 10) + x;
        const float* ac = acc + j * 5;
        out[ob + 0 * HWd + p] = ac[0];
        out[ob + 1 * HWd + p] = ac[1];
        out[ob + 2 * HWd + p] = ac[2];
        out[ob + 3 * HWd + p] = ac[3];
        out[(size_t)Bd * Cd * HWd + (size_t)b * HWd + p] = ac[4];
    }
}

// ---------------------------------------------------------------------------
extern "C" void kernel_launch(void* const* d_in, const int* in_sizes, int n_in,
                              void* d_out, int out_size) {
    const float* images = (const float*)d_in[0];
    const float* alphas = (const float*)d_in[1];
    const float* coffs  = (const float*)d_in[2];
    const float* K      = (const float*)d_in[3];
    const float* df     = (const float*)d_in[4];
    const float* eta    = (const float*)d_in[5];
    const int*   spc    = (n_in >= 7) ? (const int*)d_in[6] : nullptr;
    float* out = (float*)d_out;

    int smem_bytes = NSMP * 16 + 16                   // samples + count (16B aligned)
                   + HALO_H * HALO_S * 12;            // split records (~70 KB total)
    cudaFuncSetAttribute(render_kernel,
                         cudaFuncAttributeMaxDynamicSharedMemorySize, smem_bytes);

    dim3 rb(TILE_X, 16, 1);
    dim3 rg(Wd / TILE_X, Hd / TILE_Y, Bd);
    render_kernel<<<rg, rb, smem_bytes>>>(images, alphas, coffs, K, df, eta, spc, out);
}